// round 14
// baseline (speedup 1.0000x reference)
#include <cuda_runtime.h>
#include <cuda_fp16.h>
#include <math.h>
#include <cstdint>

// Problem constants
#define EMB   1024
#define NHEAD 16
#define HDIM  64
#define LQ    2048
#define BB    2
#define SS    2048
#define MROWS (LQ * BB)   // 4096
#define KDIM  1024

// ---------------- device scratch (no allocation allowed) ----------------
__device__ __half g_ah[3 * MROWS * KDIM];   // converted query/key/value inputs
__device__ __half g_wh[4 * EMB * EMB];      // converted w_in (3M) + w_out (1M)
__device__ __half g_qh[MROWS * EMB];        // q projection (pre-scaled by log2e/8)
__device__ __half g_kh[MROWS * EMB];
__device__ __half g_vh[MROWS * EMB];
__device__ __half g_ch[MROWS * EMB];        // attention context (f16)

// ======================= helpers =======================
__device__ __forceinline__ uint32_t smem_u32(const void* p) {
    uint32_t a;
    asm("{ .reg .u64 t; cvta.to.shared.u64 t, %1; cvt.u32.u64 %0, t; }"
        : "=r"(a) : "l"(p));
    return a;
}

__device__ __forceinline__ uint32_t packh2(float hi, float lo) {
    uint32_t r;
    asm("cvt.rn.f16x2.f32 %0, %1, %2;" : "=r"(r) : "f"(hi), "f"(lo));
    return r;
}

__device__ __forceinline__ uint32_t h2ex2(uint32_t x) {
    uint32_t r;
    asm("ex2.approx.f16x2 %0, %1;" : "=r"(r) : "r"(x));
    return r;
}

__device__ __forceinline__ float ex2f(float x) {
    float y;
    asm("ex2.approx.ftz.f32 %0, %1;" : "=f"(y) : "f"(x));
    return y;
}

__device__ __forceinline__ void mma16(float* d, uint32_t a0, uint32_t a1,
                                      uint32_t a2, uint32_t a3,
                                      uint32_t b0, uint32_t b1) {
    asm volatile(
        "mma.sync.aligned.m16n8k16.row.col.f32.f16.f16.f32 "
        "{%0,%1,%2,%3}, {%4,%5,%6,%7}, {%8,%9}, {%0,%1,%2,%3};"
        : "+f"(d[0]), "+f"(d[1]), "+f"(d[2]), "+f"(d[3])
        : "r"(a0), "r"(a1), "r"(a2), "r"(a3), "r"(b0), "r"(b1));
}

__device__ __forceinline__ void ldsm4(uint32_t& r0, uint32_t& r1,
                                      uint32_t& r2, uint32_t& r3, uint32_t addr) {
    asm volatile("ldmatrix.sync.aligned.m8n8.x4.shared.b16 {%0,%1,%2,%3}, [%4];"
                 : "=r"(r0), "=r"(r1), "=r"(r2), "=r"(r3) : "r"(addr));
}

__device__ __forceinline__ void ldsm4t(uint32_t& r0, uint32_t& r1,
                                       uint32_t& r2, uint32_t& r3, uint32_t addr) {
    asm volatile("ldmatrix.sync.aligned.m8n8.x4.trans.shared.b16 {%0,%1,%2,%3}, [%4];"
                 : "=r"(r0), "=r"(r1), "=r"(r2), "=r"(r3) : "r"(addr));
}

__device__ __forceinline__ void cpa16(uint32_t dst, const void* src) {
    asm volatile("cp.async.cg.shared.global [%0], [%1], 16;"
                 :: "r"(dst), "l"(src));
}
#define CP_COMMIT() asm volatile("cp.async.commit_group;" ::: "memory")
#define CP_WAIT1()  asm volatile("cp.async.wait_group 1;" ::: "memory")

// swizzled tile layout: 128 rows x 64 halves (128B rows), chunk ^= row&7
// tile index t -> halves offset t*8192
__device__ __forceinline__ uint32_t sw_off(int tile, int row, int chunk) {
    return (uint32_t)(tile * 8192 + row * 64 + (((chunk) ^ (row & 7)) << 3));
}

// ===========================================================================
// Fused f32 -> f16 conversion, 2 float4 per thread.
// ===========================================================================
#define N4_IN   1048576   // float4s per input tensor
#define N4_WIN  786432
#define N4_WOUT 262144
#define N4_TOT  (3 * N4_IN + N4_WIN + N4_WOUT)   // 4194304

__device__ __forceinline__ void f2h_one(int i, const float* q, const float* k,
                                        const float* v, const float* wi,
                                        const float* wo, __half* ah, __half* wh) {
    const float* src;
    uint32_t* dst;
    int li;
    if (i < 3 * N4_IN) {
        int s = i >> 20;
        li = i & (N4_IN - 1);
        src = (s == 0) ? q : (s == 1) ? k : v;
        dst = reinterpret_cast<uint32_t*>(ah) + 2 * (size_t)i;
    } else if (i < 3 * N4_IN + N4_WIN) {
        li = i - 3 * N4_IN;
        src = wi;
        dst = reinterpret_cast<uint32_t*>(wh) + 2 * (size_t)li;
    } else {
        li = i - 3 * N4_IN - N4_WIN;
        src = wo;
        dst = reinterpret_cast<uint32_t*>(wh) + 2 * (size_t)(N4_WIN + li);
    }
    float4 x = reinterpret_cast<const float4*>(src)[li];
    dst[0] = packh2(x.y, x.x);
    dst[1] = packh2(x.w, x.z);
}

__global__ void f2h_all(const float* __restrict__ q, const float* __restrict__ k,
                        const float* __restrict__ v, const float* __restrict__ wi,
                        const float* __restrict__ wo,
                        __half* __restrict__ ah, __half* __restrict__ wh)
{
    int i = blockIdx.x * blockDim.x + threadIdx.x;
    f2h_one(i, q, k, v, wi, wo, ah, wh);
    f2h_one(i + N4_TOT / 2, q, k, v, wi, wo, ah, wh);
}

// ===========================================================================
// fp16 GEMM: BK=64 swizzled stages, 3-stage cp.async, one sync per k-tile.
// C[4096,1024] = A_h @ W_h^T + bias. 8 warps (4m x 2n), warp 32m x 64n.
// Stage: A tile (128x64) + W tile (128x64) = 32KB; 3 stages = 96KB.
// ===========================================================================
#define G_SMEM (6 * 8192 * 2)   // 98304 bytes

__global__ __launch_bounds__(256, 2)
void gemm16(const __half* __restrict__ Ab, int astride_z,
            const __half* __restrict__ Wb, const float* __restrict__ bias,
            __half* o0, __half* o1, __half* o2, float* of32, float scale0)
{
    extern __shared__ __half smh[];
    const uint32_t sb = smem_u32(smh);

    const int z = blockIdx.z;
    const __half* A = Ab + (size_t)z * astride_z;
    const __half* Wz = Wb + (size_t)z * EMB * EMB;
    const float* bz = bias + z * EMB;
    __half* Ch = (z == 0) ? o0 : (z == 1) ? o1 : o2;
    const float scale = (z == 0) ? scale0 : 1.0f;

    const int tid = threadIdx.x;
    const int warp = tid >> 5;
    const int lane = tid & 31;
    const int gid = lane >> 2;
    const int tig = lane & 3;
    const int ri = lane & 7;
    const int mi = lane >> 3;
    const int wm = warp & 3;
    const int wn = warp >> 2;
    const int m0 = blockIdx.y * 128;
    const int n0 = blockIdx.x * 128;

    float acc[2][8][4];
#pragma unroll
    for (int mt = 0; mt < 2; ++mt)
#pragma unroll
        for (int nt = 0; nt < 8; ++nt)
#pragma unroll
            for (int r = 0; r < 4; ++r) acc[mt][nt][r] = 0.0f;

    // stage st: A tile index 2*st, W tile index 2*st+1. kt = 64-wide k-tile.
    auto issue = [&](int st, int kt) {
#pragma unroll
        for (int p = 0; p < 8; ++p) {
            int idx = p * 256 + tid;          // 0..2047
            int isW = idx >> 10;
            int i2 = idx & 1023;
            int row = i2 >> 3;
            int c = i2 & 7;
            const __half* src = (isW ? Wz + (size_t)(n0 + row) * KDIM
                                     : A + (size_t)(m0 + row) * KDIM)
                                + kt * 64 + c * 8;
            cpa16(sb + 2 * sw_off(2 * st + isW, row, c), src);
        }
        CP_COMMIT();
    };

    issue(0, 0);
    issue(1, 1);

    for (int kt = 0; kt < 16; ++kt) {
        const int st = kt % 3;
        CP_WAIT1();
        __syncthreads();
        if (kt + 2 < 16) issue((kt + 2) % 3, kt + 2);
        else CP_COMMIT();

#pragma unroll
        for (int ks = 0; ks < 4; ++ks) {
            uint32_t a[2][4];
#pragma unroll
            for (int mt = 0; mt < 2; ++mt)
                ldsm4(a[mt][0], a[mt][1], a[mt][2], a[mt][3],
                      sb + 2 * sw_off(2 * st, wm * 32 + mt * 16 + ri + (mi & 1) * 8,
                                      ks * 2 + (mi >> 1)));
#pragma unroll
            for (int nt2 = 0; nt2 < 4; ++nt2) {
                uint32_t b0, b1, b2, b3;
                ldsm4(b0, b1, b2, b3,
                      sb + 2 * sw_off(2 * st + 1, wn * 64 + nt2 * 16 + ri + (mi >> 1) * 8,
                                      ks * 2 + (mi & 1)));
#pragma unroll
                for (int mt = 0; mt < 2; ++mt) {
                    mma16(acc[mt][2 * nt2],     a[mt][0], a[mt][1], a[mt][2], a[mt][3], b0, b1);
                    mma16(acc[mt][2 * nt2 + 1], a[mt][0], a[mt][1], a[mt][2], a[mt][3], b2, b3);
                }
            }
        }
    }

    // epilogue
#pragma unroll
    for (int mt = 0; mt < 2; ++mt) {
        int r = m0 + wm * 32 + mt * 16 + gid;
#pragma unroll
        for (int nt = 0; nt < 8; ++nt) {
            int c = n0 + wn * 64 + nt * 8 + 2 * tig;
            float bx = bz[c], by = bz[c + 1];
            if (of32) {
                float2 p0 = make_float2(acc[mt][nt][0] + bx, acc[mt][nt][1] + by);
                float2 p1 = make_float2(acc[mt][nt][2] + bx, acc[mt][nt][3] + by);
                *reinterpret_cast<float2*>(of32 + (size_t)r * EMB + c) = p0;
                *reinterpret_cast<float2*>(of32 + (size_t)(r + 8) * EMB + c) = p1;
            } else {
                uint32_t w0 = packh2((acc[mt][nt][1] + by) * scale,
                                     (acc[mt][nt][0] + bx) * scale);
                uint32_t w1 = packh2((acc[mt][nt][3] + by) * scale,
                                     (acc[mt][nt][2] + bx) * scale);
                *reinterpret_cast<uint32_t*>(Ch + (size_t)r * EMB + c) = w0;
                *reinterpret_cast<uint32_t*>(Ch + (size_t)(r + 8) * EMB + c) = w1;
            }
        }
    }
}

// ===========================================================================
// Flash attention (round-11 numerics, known-good): f16 in/out, 3-stage
// cp.async K/V with swizzled tiles, ONE sync per KV tile, register-resident P,
// ONLINE softmax with running row max (ex2 inputs near 0 for dominant weights).
// smem tiles (128x64 halves = 16KB): Q | K0 K1 K2 | V0 V1 V2 = 114688 B
// ===========================================================================
#define F_SMEM_BYTES (7 * 8192 * 2)   // 114688

__global__ __launch_bounds__(256, 2)
void flash_attn(const __half* __restrict__ gq, const __half* __restrict__ gk,
                const __half* __restrict__ gv, __half* __restrict__ ctx)
{
    extern __shared__ __half smh[];
    const uint32_t sb = smem_u32(smh);

    const int tid = threadIdx.x;
    const int warp = tid >> 5;
    const int lane = tid & 31;
    const int gid = lane >> 2;
    const int tig = lane & 3;
    const int ri = lane & 7;
    const int mi = lane >> 3;

    const int q0 = blockIdx.x * 128;
    const int bh = blockIdx.y;
    const int b = bh & (BB - 1);
    const int h = bh >> 1;
    const size_t hoff = (size_t)h * HDIM;
    const int rowQ = warp * 16;

    auto issueKV = [&](int st, int s0) {
#pragma unroll
        for (int p = 0; p < 8; ++p) {
            int idx = p * 256 + tid;           // 0..2047
            int isV = idx >> 10;
            int i2 = idx & 1023;
            int j = i2 >> 3;
            int c = i2 & 7;
            const __half* src = (isV ? gv : gk)
                + ((size_t)(s0 + j) * BB + b) * EMB + hoff + c * 8;
            cpa16(sb + 2 * sw_off((isV ? 4 : 1) + st, j, c), src);
        }
        CP_COMMIT();
    };

    // group 0: Q + KV tile 0
#pragma unroll
    for (int p = 0; p < 4; ++p) {
        int idx = p * 256 + tid;               // 0..1023
        int i = idx >> 3;
        int c = idx & 7;
        const __half* src = gq + ((size_t)(q0 + i) * BB + b) * EMB + hoff + c * 8;
        cpa16(sb + 2 * sw_off(0, i, c), src);
    }
#pragma unroll
    for (int p = 0; p < 8; ++p) {
        int idx = p * 256 + tid;
        int isV = idx >> 10;
        int i2 = idx & 1023;
        int j = i2 >> 3;
        int c = i2 & 7;
        const __half* src = (isV ? gv : gk) + ((size_t)j * BB + b) * EMB + hoff + c * 8;
        cpa16(sb + 2 * sw_off((isV ? 4 : 1), j, c), src);
    }
    CP_COMMIT();
    issueKV(1, 128);   // group 1: KV tile 1 -> stage 1

    float m0r = -1e30f, m1r = -1e30f, l0 = 0.0f, l1 = 0.0f;
    float Of[8][4];
#pragma unroll
    for (int nt = 0; nt < 8; ++nt)
#pragma unroll
        for (int r = 0; r < 4; ++r) Of[nt][r] = 0.0f;

    const uint32_t ones = (gid == 0) ? 0x3C003C00u : 0u;  // fp16 (1,1) at n==0

    for (int t = 0; t < 16; ++t) {
        const int st = t % 3;
        CP_WAIT1();
        __syncthreads();
        // prefetch into stage (t-1)%3: its readers finished before the sync above
        if (t + 2 < 16) issueKV((t + 2) % 3, (t + 2) * 128);
        else CP_COMMIT();

        // ---- S = Q @ K^T (Q pre-scaled by log2e/8): warp 16 x 128
        float sfr[16][4];
#pragma unroll
        for (int nt = 0; nt < 16; ++nt)
#pragma unroll
            for (int r = 0; r < 4; ++r) sfr[nt][r] = 0.0f;

#pragma unroll
        for (int ks = 0; ks < 4; ++ks) {
            uint32_t a0, a1, a2, a3;
            ldsm4(a0, a1, a2, a3,
                  sb + 2 * sw_off(0, rowQ + ri + (mi & 1) * 8, ks * 2 + (mi >> 1)));
#pragma unroll
            for (int nt2 = 0; nt2 < 8; ++nt2) {
                uint32_t b0, b1, b2, b3;
                ldsm4(b0, b1, b2, b3,
                      sb + 2 * sw_off(1 + st, nt2 * 16 + ri + (mi >> 1) * 8,
                                      ks * 2 + (mi & 1)));
                mma16(sfr[2 * nt2],     a0, a1, a2, a3, b0, b1);
                mma16(sfr[2 * nt2 + 1], a0, a1, a2, a3, b2, b3);
            }
        }

        // ---- online softmax (base 2)
        float mx0 = sfr[0][0], mx1 = sfr[0][2];
#pragma unroll
        for (int nt = 0; nt < 16; ++nt) {
            mx0 = fmaxf(mx0, fmaxf(sfr[nt][0], sfr[nt][1]));
            mx1 = fmaxf(mx1, fmaxf(sfr[nt][2], sfr[nt][3]));
        }
#pragma unroll
        for (int off = 1; off <= 2; off <<= 1) {
            mx0 = fmaxf(mx0, __shfl_xor_sync(0xffffffffu, mx0, off));
            mx1 = fmaxf(mx1, __shfl_xor_sync(0xffffffffu, mx1, off));
        }
        float mn0 = fmaxf(m0r, mx0), mn1 = fmaxf(m1r, mx1);
        float c0 = ex2f(m0r - mn0), c1 = ex2f(m1r - mn1);
        m0r = mn0; m1r = mn1;

        // P = 2^(s-mn), packed f16x2 — these ARE the PV A-fragments
        uint32_t pk0[16], pk1[16];
#pragma unroll
        for (int nt = 0; nt < 16; ++nt) {
            pk0[nt] = h2ex2(packh2(sfr[nt][1] - mn0, sfr[nt][0] - mn0));
            pk1[nt] = h2ex2(packh2(sfr[nt][3] - mn1, sfr[nt][2] - mn1));
        }
#pragma unroll
        for (int nt = 0; nt < 8; ++nt) {
            Of[nt][0] *= c0; Of[nt][1] *= c0;
            Of[nt][2] *= c1; Of[nt][3] *= c1;
        }
        float lacc[4] = {0.0f, 0.0f, 0.0f, 0.0f};

        // ---- O += P @ V (+ row sums via ones column): k = 128 (8 steps)
#pragma unroll
        for (int ks = 0; ks < 8; ++ks) {
            uint32_t a0 = pk0[2 * ks], a1 = pk1[2 * ks];
            uint32_t a2 = pk0[2 * ks + 1], a3 = pk1[2 * ks + 1];
#pragma unroll
            for (int dt2 = 0; dt2 < 4; ++dt2) {
                uint32_t b0, b1, b2, b3;
                ldsm4t(b0, b1, b2, b3,
                       sb + 2 * sw_off(4 + st, ks * 16 + ri + (mi & 1) * 8,
                                       dt2 * 2 + (mi >> 1)));
                mma16(Of[2 * dt2],     a0, a1, a2, a3, b0, b1);
                mma16(Of[2 * dt2 + 1], a0, a1, a2, a3, b2, b3);
            }
            mma16(lacc, a0, a1, a2, a3, ones, ones);
        }
        l0 = l0 * c0 + lacc[0];
        l1 = l1 * c1 + lacc[2];
    }

    // broadcast row sums from tig==0 lanes, normalize, store f16 ctx
    const int src = lane & ~3;
    float l0b = __shfl_sync(0xffffffffu, l0, src);
    float l1b = __shfl_sync(0xffffffffu, l1, src);
    float i0 = 1.0f / l0b, i1 = 1.0f / l1b;
    int r = q0 + rowQ + gid;
#pragma unroll
    for (int nt = 0; nt < 8; ++nt) {
        int d = nt * 8 + 2 * tig;
        uint32_t w0 = packh2(Of[nt][1] * i0, Of[nt][0] * i0);
        uint32_t w1 = packh2(Of[nt][3] * i1, Of[nt][2] * i1);
        *reinterpret_cast<uint32_t*>(ctx + ((size_t)r * BB + b) * EMB + hoff + d) = w0;
        *reinterpret_cast<uint32_t*>(ctx + ((size_t)(r + 8) * BB + b) * EMB + hoff + d) = w1;
    }
}

// ---------------------------------------------------------------------------
extern "C" void kernel_launch(void* const* d_in, const int* in_sizes, int n_in,
                              void* d_out, int out_size)
{
    const float* query = (const float*)d_in[0];
    const float* key   = (const float*)d_in[1];
    const float* value = (const float*)d_in[2];
    const float* w_in  = (const float*)d_in[3];
    const float* b_in  = (const float*)d_in[4];
    const float* w_out = (const float*)d_in[5];
    const float* b_out = (const float*)d_in[6];
    float* out = (float*)d_out;

    __half *ah, *wh, *qh, *kh, *vh, *ch;
    cudaGetSymbolAddress((void**)&ah, g_ah);
    cudaGetSymbolAddress((void**)&wh, g_wh);
    cudaGetSymbolAddress((void**)&qh, g_qh);
    cudaGetSymbolAddress((void**)&kh, g_kh);
    cudaGetSymbolAddress((void**)&vh, g_vh);
    cudaGetSymbolAddress((void**)&ch, g_ch);

    const float QSC = 0.180336880f;  // log2(e) / 8

    f2h_all<<<N4_TOT / 2 / 256, 256>>>(query, key, value, w_in, w_out, ah, wh);

    cudaFuncSetAttribute(gemm16, cudaFuncAttributeMaxDynamicSharedMemorySize, G_SMEM);
    cudaFuncSetAttribute(flash_attn, cudaFuncAttributeMaxDynamicSharedMemorySize, F_SMEM_BYTES);

    // fused QKV projection (q pre-scaled by QSC)
    dim3 qkv_grid(EMB / 128, MROWS / 128, 3);
    gemm16<<<qkv_grid, 256, G_SMEM>>>(ah, MROWS * KDIM, wh, b_in, qh, kh, vh, nullptr, QSC);

    dim3 flash_grid(LQ / 128, BB * NHEAD);  // (16, 32)
    flash_attn<<<flash_grid, 256, F_SMEM_BYTES>>>(qh, kh, vh, ch);

    // out projection -> f32 d_out
    dim3 out_grid(EMB / 128, MROWS / 128, 1);
    gemm16<<<out_grid, 256, G_SMEM>>>(ch, 0, wh + 3 * EMB * EMB, b_out,
                                      nullptr, nullptr, nullptr, out, 1.0f);
}

// round 15
// speedup vs baseline: 1.3327x; 1.3327x over previous
#include <cuda_runtime.h>
#include <cuda_fp16.h>
#include <math.h>
#include <cstdint>

// Problem constants
#define EMB   1024
#define NHEAD 16
#define HDIM  64
#define LQ    2048
#define BB    2
#define SS    2048
#define MROWS (LQ * BB)   // 4096
#define KDIM  1024

// ---------------- device scratch (no allocation allowed) ----------------
__device__ __half g_ah[3 * MROWS * KDIM];   // converted query/key/value inputs
__device__ __half g_wh[4 * EMB * EMB];      // converted w_in (3M) + w_out (1M)
__device__ __half g_qh[MROWS * EMB];        // q projection (pre-scaled by log2e/8)
__device__ __half g_kh[MROWS * EMB];
__device__ __half g_vh[MROWS * EMB];
__device__ __half g_ch[MROWS * EMB];        // attention context (f16)

// ======================= helpers =======================
__device__ __forceinline__ uint32_t smem_u32(const void* p) {
    uint32_t a;
    asm("{ .reg .u64 t; cvta.to.shared.u64 t, %1; cvt.u32.u64 %0, t; }"
        : "=r"(a) : "l"(p));
    return a;
}

__device__ __forceinline__ uint32_t packh2(float hi, float lo) {
    uint32_t r;
    asm("cvt.rn.f16x2.f32 %0, %1, %2;" : "=r"(r) : "f"(hi), "f"(lo));
    return r;
}

__device__ __forceinline__ uint32_t h2ex2(uint32_t x) {
    uint32_t r;
    asm("ex2.approx.f16x2 %0, %1;" : "=r"(r) : "r"(x));
    return r;
}

__device__ __forceinline__ float ex2f(float x) {
    float y;
    asm("ex2.approx.ftz.f32 %0, %1;" : "=f"(y) : "f"(x));
    return y;
}

__device__ __forceinline__ void mma16(float* d, uint32_t a0, uint32_t a1,
                                      uint32_t a2, uint32_t a3,
                                      uint32_t b0, uint32_t b1) {
    asm volatile(
        "mma.sync.aligned.m16n8k16.row.col.f32.f16.f16.f32 "
        "{%0,%1,%2,%3}, {%4,%5,%6,%7}, {%8,%9}, {%0,%1,%2,%3};"
        : "+f"(d[0]), "+f"(d[1]), "+f"(d[2]), "+f"(d[3])
        : "r"(a0), "r"(a1), "r"(a2), "r"(a3), "r"(b0), "r"(b1));
}

__device__ __forceinline__ void ldsm4(uint32_t& r0, uint32_t& r1,
                                      uint32_t& r2, uint32_t& r3, uint32_t addr) {
    asm volatile("ldmatrix.sync.aligned.m8n8.x4.shared.b16 {%0,%1,%2,%3}, [%4];"
                 : "=r"(r0), "=r"(r1), "=r"(r2), "=r"(r3) : "r"(addr));
}

__device__ __forceinline__ void ldsm4t(uint32_t& r0, uint32_t& r1,
                                       uint32_t& r2, uint32_t& r3, uint32_t addr) {
    asm volatile("ldmatrix.sync.aligned.m8n8.x4.trans.shared.b16 {%0,%1,%2,%3}, [%4];"
                 : "=r"(r0), "=r"(r1), "=r"(r2), "=r"(r3) : "r"(addr));
}

__device__ __forceinline__ void cpa16(uint32_t dst, const void* src) {
    asm volatile("cp.async.cg.shared.global [%0], [%1], 16;"
                 :: "r"(dst), "l"(src));
}
#define CP_COMMIT() asm volatile("cp.async.commit_group;" ::: "memory")
#define CP_WAIT1()  asm volatile("cp.async.wait_group 1;" ::: "memory")
#define CP_WAIT2()  asm volatile("cp.async.wait_group 2;" ::: "memory")

// swizzled tile layout (flash): 128 rows x 64 halves (128B rows), chunk ^= row&7
__device__ __forceinline__ uint32_t sw_off(int tile, int row, int chunk) {
    return (uint32_t)(tile * 8192 + row * 64 + (((chunk) ^ (row & 7)) << 3));
}

// ===========================================================================
// Fused f32 -> f16 conversion, 2 float4 per thread.
// ===========================================================================
#define N4_IN   1048576   // float4s per input tensor
#define N4_WIN  786432
#define N4_WOUT 262144
#define N4_TOT  (3 * N4_IN + N4_WIN + N4_WOUT)   // 4194304

__device__ __forceinline__ void f2h_one(int i, const float* q, const float* k,
                                        const float* v, const float* wi,
                                        const float* wo, __half* ah, __half* wh) {
    const float* src;
    uint32_t* dst;
    int li;
    if (i < 3 * N4_IN) {
        int s = i >> 20;
        li = i & (N4_IN - 1);
        src = (s == 0) ? q : (s == 1) ? k : v;
        dst = reinterpret_cast<uint32_t*>(ah) + 2 * (size_t)i;
    } else if (i < 3 * N4_IN + N4_WIN) {
        li = i - 3 * N4_IN;
        src = wi;
        dst = reinterpret_cast<uint32_t*>(wh) + 2 * (size_t)li;
    } else {
        li = i - 3 * N4_IN - N4_WIN;
        src = wo;
        dst = reinterpret_cast<uint32_t*>(wh) + 2 * (size_t)(N4_WIN + li);
    }
    float4 x = reinterpret_cast<const float4*>(src)[li];
    dst[0] = packh2(x.y, x.x);
    dst[1] = packh2(x.w, x.z);
}

__global__ void f2h_all(const float* __restrict__ q, const float* __restrict__ k,
                        const float* __restrict__ v, const float* __restrict__ wi,
                        const float* __restrict__ wo,
                        __half* __restrict__ ah, __half* __restrict__ wh)
{
    int i = blockIdx.x * blockDim.x + threadIdx.x;
    f2h_one(i, q, k, v, wi, wo, ah, wh);
    f2h_one(i + N4_TOT / 2, q, k, v, wi, wo, ah, wh);
}

// ===========================================================================
// fp16 GEMM (round-11 layout, 4-stage): BK=32, GPH=40, cp.async pipeline with
// lookahead depth 3, one sync per k-tile.
// C[4096,1024] = A_h @ W_h^T + bias. 8 warps (4m x 2n), warp 32m x 64n.
// Stage = A(128x32) + W(128x32) at pitch 40 = 20480 B; 4 stages = 81920 B.
// ===========================================================================
#define GPH 40
#define STG_A (128 * GPH)       // halves per A stage
#define STG (2 * 128 * GPH)     // halves per stage (A + W)
#define G_SMEM (4 * STG * 2)    // 81920 bytes

__global__ __launch_bounds__(256, 2)
void gemm16(const __half* __restrict__ Ab, int astride_z,
            const __half* __restrict__ Wb, const float* __restrict__ bias,
            __half* o0, __half* o1, __half* o2, float* of32, float scale0)
{
    extern __shared__ __half smh[];
    const uint32_t sb = smem_u32(smh);

    const int z = blockIdx.z;
    const __half* A = Ab + (size_t)z * astride_z;
    const __half* Wz = Wb + (size_t)z * EMB * EMB;
    const float* bz = bias + z * EMB;
    __half* Ch = (z == 0) ? o0 : (z == 1) ? o1 : o2;
    const float scale = (z == 0) ? scale0 : 1.0f;

    const int tid = threadIdx.x;
    const int warp = tid >> 5;
    const int lane = tid & 31;
    const int gid = lane >> 2;
    const int tig = lane & 3;
    const int ri = lane & 7;
    const int mi = lane >> 3;
    const int wm = warp & 3;
    const int wn = warp >> 2;
    const int m0 = blockIdx.y * 128;
    const int n0 = blockIdx.x * 128;

    float acc[2][8][4];
#pragma unroll
    for (int mt = 0; mt < 2; ++mt)
#pragma unroll
        for (int nt = 0; nt < 8; ++nt)
#pragma unroll
            for (int r = 0; r < 4; ++r) acc[mt][nt][r] = 0.0f;

    auto issue = [&](int st, int kt) {
#pragma unroll
        for (int p = 0; p < 4; ++p) {
            int idx = p * 256 + tid;
            int isW = idx >> 9;
            int i2 = idx & 511;
            int row = i2 >> 2;
            int c = i2 & 3;
            const __half* src = (isW ? Wz + (size_t)(n0 + row) * KDIM
                                     : A + (size_t)(m0 + row) * KDIM)
                                + kt * 32 + c * 8;
            uint32_t dst = sb + (uint32_t)(st * STG + isW * STG_A + row * GPH) * 2
                           + (uint32_t)c * 16;
            cpa16(dst, src);
        }
        CP_COMMIT();
    };

    issue(0, 0);
    issue(1, 1);
    issue(2, 2);

    for (int kt = 0; kt < 32; ++kt) {
        const int st = kt & 3;
        CP_WAIT2();
        __syncthreads();
        // issue into stage (kt+3)&3 == (kt-1)&3: its readers finished before the sync
        if (kt + 3 < 32) issue((kt + 3) & 3, kt + 3);
        else CP_COMMIT();

        const uint32_t baseA = sb + (uint32_t)(st * STG) * 2;
        const uint32_t baseW = sb + (uint32_t)(st * STG + STG_A) * 2;
#pragma unroll
        for (int ks = 0; ks < 2; ++ks) {
            const int k0 = ks * 16;
            uint32_t a[2][4];
#pragma unroll
            for (int mt = 0; mt < 2; ++mt) {
                uint32_t addr = baseA + 2 * ((wm * 32 + mt * 16 + ri + (mi & 1) * 8) * GPH
                                             + k0 + (mi >> 1) * 8);
                ldsm4(a[mt][0], a[mt][1], a[mt][2], a[mt][3], addr);
            }
#pragma unroll
            for (int nt2 = 0; nt2 < 4; ++nt2) {
                uint32_t b0, b1, b2, b3;
                uint32_t addr = baseW + 2 * ((wn * 64 + nt2 * 16 + ri + (mi >> 1) * 8) * GPH
                                             + k0 + (mi & 1) * 8);
                ldsm4(b0, b1, b2, b3, addr);
#pragma unroll
                for (int mt = 0; mt < 2; ++mt) {
                    mma16(acc[mt][2 * nt2],     a[mt][0], a[mt][1], a[mt][2], a[mt][3], b0, b1);
                    mma16(acc[mt][2 * nt2 + 1], a[mt][0], a[mt][1], a[mt][2], a[mt][3], b2, b3);
                }
            }
        }
    }

    // epilogue
#pragma unroll
    for (int mt = 0; mt < 2; ++mt) {
        int r = m0 + wm * 32 + mt * 16 + gid;
#pragma unroll
        for (int nt = 0; nt < 8; ++nt) {
            int c = n0 + wn * 64 + nt * 8 + 2 * tig;
            float bx = bz[c], by = bz[c + 1];
            if (of32) {
                float2 p0 = make_float2(acc[mt][nt][0] + bx, acc[mt][nt][1] + by);
                float2 p1 = make_float2(acc[mt][nt][2] + bx, acc[mt][nt][3] + by);
                *reinterpret_cast<float2*>(of32 + (size_t)r * EMB + c) = p0;
                *reinterpret_cast<float2*>(of32 + (size_t)(r + 8) * EMB + c) = p1;
            } else {
                uint32_t w0 = packh2((acc[mt][nt][1] + by) * scale,
                                     (acc[mt][nt][0] + bx) * scale);
                uint32_t w1 = packh2((acc[mt][nt][3] + by) * scale,
                                     (acc[mt][nt][2] + bx) * scale);
                *reinterpret_cast<uint32_t*>(Ch + (size_t)r * EMB + c) = w0;
                *reinterpret_cast<uint32_t*>(Ch + (size_t)(r + 8) * EMB + c) = w1;
            }
        }
    }
}

// ===========================================================================
// Flash attention (round-11, known-good, UNCHANGED): f16 in/out, 3-stage
// cp.async K/V with swizzled tiles, ONE sync per KV tile, register-resident P,
// online softmax with running row max. smem: Q | K0 K1 K2 | V0 V1 V2 = 114688 B
// ===========================================================================
#define F_SMEM_BYTES (7 * 8192 * 2)   // 114688

__global__ __launch_bounds__(256, 2)
void flash_attn(const __half* __restrict__ gq, const __half* __restrict__ gk,
                const __half* __restrict__ gv, __half* __restrict__ ctx)
{
    extern __shared__ __half smh[];
    const uint32_t sb = smem_u32(smh);

    const int tid = threadIdx.x;
    const int warp = tid >> 5;
    const int lane = tid & 31;
    const int gid = lane >> 2;
    const int tig = lane & 3;
    const int ri = lane & 7;
    const int mi = lane >> 3;

    const int q0 = blockIdx.x * 128;
    const int bh = blockIdx.y;
    const int b = bh & (BB - 1);
    const int h = bh >> 1;
    const size_t hoff = (size_t)h * HDIM;
    const int rowQ = warp * 16;

    auto issueKV = [&](int st, int s0) {
#pragma unroll
        for (int p = 0; p < 8; ++p) {
            int idx = p * 256 + tid;           // 0..2047
            int isV = idx >> 10;
            int i2 = idx & 1023;
            int j = i2 >> 3;
            int c = i2 & 7;
            const __half* src = (isV ? gv : gk)
                + ((size_t)(s0 + j) * BB + b) * EMB + hoff + c * 8;
            cpa16(sb + 2 * sw_off((isV ? 4 : 1) + st, j, c), src);
        }
        CP_COMMIT();
    };

    // group 0: Q + KV tile 0
#pragma unroll
    for (int p = 0; p < 4; ++p) {
        int idx = p * 256 + tid;               // 0..1023
        int i = idx >> 3;
        int c = idx & 7;
        const __half* src = gq + ((size_t)(q0 + i) * BB + b) * EMB + hoff + c * 8;
        cpa16(sb + 2 * sw_off(0, i, c), src);
    }
#pragma unroll
    for (int p = 0; p < 8; ++p) {
        int idx = p * 256 + tid;
        int isV = idx >> 10;
        int i2 = idx & 1023;
        int j = i2 >> 3;
        int c = i2 & 7;
        const __half* src = (isV ? gv : gk) + ((size_t)j * BB + b) * EMB + hoff + c * 8;
        cpa16(sb + 2 * sw_off((isV ? 4 : 1), j, c), src);
    }
    CP_COMMIT();
    issueKV(1, 128);   // group 1: KV tile 1 -> stage 1

    float m0r = -1e30f, m1r = -1e30f, l0 = 0.0f, l1 = 0.0f;
    float Of[8][4];
#pragma unroll
    for (int nt = 0; nt < 8; ++nt)
#pragma unroll
        for (int r = 0; r < 4; ++r) Of[nt][r] = 0.0f;

    const uint32_t ones = (gid == 0) ? 0x3C003C00u : 0u;  // fp16 (1,1) at n==0

    for (int t = 0; t < 16; ++t) {
        const int st = t % 3;
        CP_WAIT1();
        __syncthreads();
        // prefetch into stage (t-1)%3: its readers finished before the sync above
        if (t + 2 < 16) issueKV((t + 2) % 3, (t + 2) * 128);
        else CP_COMMIT();

        // ---- S = Q @ K^T (Q pre-scaled by log2e/8): warp 16 x 128
        float sfr[16][4];
#pragma unroll
        for (int nt = 0; nt < 16; ++nt)
#pragma unroll
            for (int r = 0; r < 4; ++r) sfr[nt][r] = 0.0f;

#pragma unroll
        for (int ks = 0; ks < 4; ++ks) {
            uint32_t a0, a1, a2, a3;
            ldsm4(a0, a1, a2, a3,
                  sb + 2 * sw_off(0, rowQ + ri + (mi & 1) * 8, ks * 2 + (mi >> 1)));
#pragma unroll
            for (int nt2 = 0; nt2 < 8; ++nt2) {
                uint32_t b0, b1, b2, b3;
                ldsm4(b0, b1, b2, b3,
                      sb + 2 * sw_off(1 + st, nt2 * 16 + ri + (mi >> 1) * 8,
                                      ks * 2 + (mi & 1)));
                mma16(sfr[2 * nt2],     a0, a1, a2, a3, b0, b1);
                mma16(sfr[2 * nt2 + 1], a0, a1, a2, a3, b2, b3);
            }
        }

        // ---- online softmax (base 2)
        float mx0 = sfr[0][0], mx1 = sfr[0][2];
#pragma unroll
        for (int nt = 0; nt < 16; ++nt) {
            mx0 = fmaxf(mx0, fmaxf(sfr[nt][0], sfr[nt][1]));
            mx1 = fmaxf(mx1, fmaxf(sfr[nt][2], sfr[nt][3]));
        }
#pragma unroll
        for (int off = 1; off <= 2; off <<= 1) {
            mx0 = fmaxf(mx0, __shfl_xor_sync(0xffffffffu, mx0, off));
            mx1 = fmaxf(mx1, __shfl_xor_sync(0xffffffffu, mx1, off));
        }
        float mn0 = fmaxf(m0r, mx0), mn1 = fmaxf(m1r, mx1);
        float c0 = ex2f(m0r - mn0), c1 = ex2f(m1r - mn1);
        m0r = mn0; m1r = mn1;

        // P = 2^(s-mn), packed f16x2 — these ARE the PV A-fragments
        uint32_t pk0[16], pk1[16];
#pragma unroll
        for (int nt = 0; nt < 16; ++nt) {
            pk0[nt] = h2ex2(packh2(sfr[nt][1] - mn0, sfr[nt][0] - mn0));
            pk1[nt] = h2ex2(packh2(sfr[nt][3] - mn1, sfr[nt][2] - mn1));
        }
#pragma unroll
        for (int nt = 0; nt < 8; ++nt) {
            Of[nt][0] *= c0; Of[nt][1] *= c0;
            Of[nt][2] *= c1; Of[nt][3] *= c1;
        }
        float lacc[4] = {0.0f, 0.0f, 0.0f, 0.0f};

        // ---- O += P @ V (+ row sums via ones column): k = 128 (8 steps)
#pragma unroll
        for (int ks = 0; ks < 8; ++ks) {
            uint32_t a0 = pk0[2 * ks], a1 = pk1[2 * ks];
            uint32_t a2 = pk0[2 * ks + 1], a3 = pk1[2 * ks + 1];
#pragma unroll
            for (int dt2 = 0; dt2 < 4; ++dt2) {
                uint32_t b0, b1, b2, b3;
                ldsm4t(b0, b1, b2, b3,
                       sb + 2 * sw_off(4 + st, ks * 16 + ri + (mi & 1) * 8,
                                       dt2 * 2 + (mi >> 1)));
                mma16(Of[2 * dt2],     a0, a1, a2, a3, b0, b1);
                mma16(Of[2 * dt2 + 1], a0, a1, a2, a3, b2, b3);
            }
            mma16(lacc, a0, a1, a2, a3, ones, ones);
        }
        l0 = l0 * c0 + lacc[0];
        l1 = l1 * c1 + lacc[2];
    }

    // broadcast row sums from tig==0 lanes, normalize, store f16 ctx
    const int src = lane & ~3;
    float l0b = __shfl_sync(0xffffffffu, l0, src);
    float l1b = __shfl_sync(0xffffffffu, l1, src);
    float i0 = 1.0f / l0b, i1 = 1.0f / l1b;
    int r = q0 + rowQ + gid;
#pragma unroll
    for (int nt = 0; nt < 8; ++nt) {
        int d = nt * 8 + 2 * tig;
        uint32_t w0 = packh2(Of[nt][1] * i0, Of[nt][0] * i0);
        uint32_t w1 = packh2(Of[nt][3] * i1, Of[nt][2] * i1);
        *reinterpret_cast<uint32_t*>(ctx + ((size_t)r * BB + b) * EMB + hoff + d) = w0;
        *reinterpret_cast<uint32_t*>(ctx + ((size_t)(r + 8) * BB + b) * EMB + hoff + d) = w1;
    }
}

// ---------------------------------------------------------------------------
extern "C" void kernel_launch(void* const* d_in, const int* in_sizes, int n_in,
                              void* d_out, int out_size)
{
    const float* query = (const float*)d_in[0];
    const float* key   = (const float*)d_in[1];
    const float* value = (const float*)d_in[2];
    const float* w_in  = (const float*)d_in[3];
    const float* b_in  = (const float*)d_in[4];
    const float* w_out = (const float*)d_in[5];
    const float* b_out = (const float*)d_in[6];
    float* out = (float*)d_out;

    __half *ah, *wh, *qh, *kh, *vh, *ch;
    cudaGetSymbolAddress((void**)&ah, g_ah);
    cudaGetSymbolAddress((void**)&wh, g_wh);
    cudaGetSymbolAddress((void**)&qh, g_qh);
    cudaGetSymbolAddress((void**)&kh, g_kh);
    cudaGetSymbolAddress((void**)&vh, g_vh);
    cudaGetSymbolAddress((void**)&ch, g_ch);

    const float QSC = 0.180336880f;  // log2(e) / 8

    f2h_all<<<N4_TOT / 2 / 256, 256>>>(query, key, value, w_in, w_out, ah, wh);

    cudaFuncSetAttribute(gemm16, cudaFuncAttributeMaxDynamicSharedMemorySize, G_SMEM);
    cudaFuncSetAttribute(flash_attn, cudaFuncAttributeMaxDynamicSharedMemorySize, F_SMEM_BYTES);

    // fused QKV projection (q pre-scaled by QSC)
    dim3 qkv_grid(EMB / 128, MROWS / 128, 3);
    gemm16<<<qkv_grid, 256, G_SMEM>>>(ah, MROWS * KDIM, wh, b_in, qh, kh, vh, nullptr, QSC);

    dim3 flash_grid(LQ / 128, BB * NHEAD);  // (16, 32)
    flash_attn<<<flash_grid, 256, F_SMEM_BYTES>>>(qh, kh, vh, ch);

    // out projection -> f32 d_out
    dim3 out_grid(EMB / 128, MROWS / 128, 1);
    gemm16<<<out_grid, 256, G_SMEM>>>(ch, 0, wh + 3 * EMB * EMB, b_out,
                                      nullptr, nullptr, nullptr, out, 1.0f);
}